// round 12
// baseline (speedup 1.0000x reference)
#include <cuda_runtime.h>
#include <cuda_bf16.h>
#include <cstdint>

#define BB 2
#define LL 2048
#define DD 1024
#define HH 16
#define DHH 64
#define BH (BB*HH)
#define MROWS (BB*LL)           // 4096
#define OUT_ELEMS (MROWS*DD)
#define LN_EPS 1e-5f

// ---------------------------------------------------------------------------
// Static device scratch
// ---------------------------------------------------------------------------
__device__ __nv_bfloat16 g_xq_h[MROWS*DD], g_xq_l[MROWS*DD];
__device__ __nv_bfloat16 g_xk_h[MROWS*DD], g_xk_l[MROWS*DD];
__device__ __nv_bfloat16 g_xv_h[MROWS*DD], g_xv_l[MROWS*DD];
__device__ __nv_bfloat16 g_wq_h[DD*DD], g_wq_l[DD*DD];
__device__ __nv_bfloat16 g_wk_h[DD*DD], g_wk_l[DD*DD];
__device__ __nv_bfloat16 g_wv_h[DD*DD], g_wv_l[DD*DD];
__device__ __nv_bfloat16 g_wo_h[DD*DD], g_wo_l[DD*DD];
__device__ __nv_bfloat16 g_Qh[MROWS*DD], g_Ql[MROWS*DD];
__device__ __nv_bfloat16 g_Kh[MROWS*DD], g_Kl[MROWS*DD];
__device__ __nv_bfloat16 g_Vth[MROWS*DD], g_Vtl[MROWS*DD];  // [n][c][k]
__device__ __nv_bfloat16 g_ctxh[MROWS*DD], g_ctxl[MROWS*DD];
__device__ float g_rinv[(long)BH*LL];
__device__ float g_proj[MROWS*DD];

// ---------------------------------------------------------------------------
// PTX helpers
// ---------------------------------------------------------------------------
__device__ __forceinline__ uint32_t smem_u32(const void* p) {
    uint32_t a;
    asm("{ .reg .u64 t; cvta.to.shared.u64 t, %1; cvt.u32.u64 %0, t; }" : "=r"(a) : "l"(p));
    return a;
}

#define LDMX4(r0,r1,r2,r3,addr) \
    asm volatile("ldmatrix.sync.aligned.m8n8.x4.shared.b16 {%0,%1,%2,%3}, [%4];" \
        : "=r"(r0), "=r"(r1), "=r"(r2), "=r"(r3) : "r"(addr))

#define MMA_BF16(d, a, b0v, b1v) \
    asm volatile("mma.sync.aligned.m16n8k16.row.col.f32.bf16.bf16.f32 " \
        "{%0,%1,%2,%3},{%4,%5,%6,%7},{%8,%9},{%0,%1,%2,%3};" \
        : "+f"((d)[0]), "+f"((d)[1]), "+f"((d)[2]), "+f"((d)[3]) \
        : "r"((a)[0]), "r"((a)[1]), "r"((a)[2]), "r"((a)[3]), "r"(b0v), "r"(b1v))

// MMA with A given as 4 explicit regs
#define MMA_BF16R(d, a0,a1,a2,a3, b0v, b1v) \
    asm volatile("mma.sync.aligned.m16n8k16.row.col.f32.bf16.bf16.f32 " \
        "{%0,%1,%2,%3},{%4,%5,%6,%7},{%8,%9},{%0,%1,%2,%3};" \
        : "+f"((d)[0]), "+f"((d)[1]), "+f"((d)[2]), "+f"((d)[3]) \
        : "r"(a0), "r"(a1), "r"(a2), "r"(a3), "r"(b0v), "r"(b1v))

__device__ __forceinline__ void cp16(uint32_t dst, const void* src) {
    asm volatile("cp.async.cg.shared.global [%0], [%1], 16;" :: "r"(dst), "l"(src));
}
#define CP_COMMIT() asm volatile("cp.async.commit_group;" ::: "memory")
#define CP_WAIT0()  asm volatile("cp.async.wait_group 0;" ::: "memory")
#define CP_WAIT1()  asm volatile("cp.async.wait_group 1;" ::: "memory")

__device__ __forceinline__ void lda_frag(uint32_t a[4], uint32_t base, int mbase, int ks, int lane) {
    int row = mbase + (lane & 7) + ((lane >> 3) & 1) * 8;
    int col = ks + (lane >> 4) * 8;
    LDMX4(a[0], a[1], a[2], a[3], base + row * 80 + col * 2);
}
__device__ __forceinline__ void ldb_frag(uint32_t b[4], uint32_t base, int nbase, int ks, int lane) {
    int r = lane & 7, gp = lane >> 3;
    int n = nbase + (gp >> 1) * 8 + r;
    int col = ks + (gp & 1) * 8;
    LDMX4(b[0], b[1], b[2], b[3], base + n * 80 + col * 2);
}

__device__ __forceinline__ void load32_async(const __nv_bfloat16* __restrict__ src, long ld,
                                             int R, uint32_t base, int tid) {
    for (int i = tid; i < R * 4; i += 256) {
        int row = i >> 2, q = i & 3;
        cp16(base + row * 80 + q * 16, src + (long)row * ld + q * 8);
    }
}

__device__ __forceinline__ void split2(float v, unsigned short& h, unsigned short& l) {
    __nv_bfloat16 bh = __float2bfloat16(v);
    __nv_bfloat16 bl = __float2bfloat16(v - __bfloat162float(bh));
    h = __bfloat16_as_ushort(bh); l = __bfloat16_as_ushort(bl);
}
__device__ __forceinline__ uint32_t pack_hi(float x, float y) {
    unsigned short hx = __bfloat16_as_ushort(__float2bfloat16(x));
    unsigned short hy = __bfloat16_as_ushort(__float2bfloat16(y));
    return (uint32_t)hx | ((uint32_t)hy << 16);
}
__device__ __forceinline__ uint32_t pack_lo(float x, float y) {
    float rx = x - __bfloat162float(__float2bfloat16(x));
    float ry = y - __bfloat162float(__float2bfloat16(y));
    unsigned short lx = __bfloat16_as_ushort(__float2bfloat16(rx));
    unsigned short ly = __bfloat16_as_ushort(__float2bfloat16(ry));
    return (uint32_t)lx | ((uint32_t)ly << 16);
}

// ---------------------------------------------------------------------------
// fp32 -> (hi,lo) split (merged launches)
// ---------------------------------------------------------------------------
__global__ void __launch_bounds__(256) split_inputs_kernel(
    const float* __restrict__ s0, const float* __restrict__ s1, const float* __restrict__ s2)
{
    const int which = blockIdx.y;
    const float* src = which == 0 ? s0 : which == 1 ? s1 : s2;
    __nv_bfloat16* hi = which == 0 ? g_xq_h : which == 1 ? g_xk_h : g_xv_h;
    __nv_bfloat16* lo = which == 0 ? g_xq_l : which == 1 ? g_xk_l : g_xv_l;
    long i = (long)blockIdx.x * 256 + threadIdx.x;
    float4 v = reinterpret_cast<const float4*>(src)[i];
    unsigned short h0,h1,h2,h3,l0,l1,l2,l3;
    split2(v.x,h0,l0); split2(v.y,h1,l1); split2(v.z,h2,l2); split2(v.w,h3,l3);
    uint2 uh, ul;
    uh.x = (uint32_t)h0 | ((uint32_t)h1 << 16); uh.y = (uint32_t)h2 | ((uint32_t)h3 << 16);
    ul.x = (uint32_t)l0 | ((uint32_t)l1 << 16); ul.y = (uint32_t)l2 | ((uint32_t)l3 << 16);
    reinterpret_cast<uint2*>(hi)[i] = uh;
    reinterpret_cast<uint2*>(lo)[i] = ul;
}

__global__ void __launch_bounds__(256) split_weights_kernel(
    const float* __restrict__ s0, const float* __restrict__ s1,
    const float* __restrict__ s2, const float* __restrict__ s3)
{
    const int which = blockIdx.y;
    const float* src = which == 0 ? s0 : which == 1 ? s1 : which == 2 ? s2 : s3;
    __nv_bfloat16* hi = which == 0 ? g_wq_h : which == 1 ? g_wk_h : which == 2 ? g_wv_h : g_wo_h;
    __nv_bfloat16* lo = which == 0 ? g_wq_l : which == 1 ? g_wk_l : which == 2 ? g_wv_l : g_wo_l;
    long i = (long)blockIdx.x * 256 + threadIdx.x;
    float4 v = reinterpret_cast<const float4*>(src)[i];
    unsigned short h0,h1,h2,h3,l0,l1,l2,l3;
    split2(v.x,h0,l0); split2(v.y,h1,l1); split2(v.z,h2,l2); split2(v.w,h3,l3);
    uint2 uh, ul;
    uh.x = (uint32_t)h0 | ((uint32_t)h1 << 16); uh.y = (uint32_t)h2 | ((uint32_t)h3 << 16);
    ul.x = (uint32_t)l0 | ((uint32_t)l1 << 16); ul.y = (uint32_t)l2 | ((uint32_t)l3 << 16);
    reinterpret_cast<uint2*>(hi)[i] = uh;
    reinterpret_cast<uint2*>(lo)[i] = ul;
}

// ---------------------------------------------------------------------------
// Shared 3-stage GEMM mainloop (block 128x128, BK=32, K=1024)
// ---------------------------------------------------------------------------
#define PROJ_DSMEM (3*40960)
__device__ __forceinline__ void proj_mainloop(
    const __nv_bfloat16* __restrict__ Ah_, const __nv_bfloat16* __restrict__ Al_,
    const __nv_bfloat16* __restrict__ Bh_, const __nv_bfloat16* __restrict__ Bl_,
    uint32_t sb, int tid, int lane, int wm, int wn, float acc[4][4][4])
{
    const int NC = DD / 32;   // 32
    #pragma unroll
    for (int p = 0; p < 2; p++) {
        uint32_t s = sb + p * 40960;
        load32_async(Ah_ + p*32, DD, 128, s,         tid);
        load32_async(Al_ + p*32, DD, 128, s + 10240, tid);
        load32_async(Bh_ + p*32, DD, 128, s + 20480, tid);
        load32_async(Bl_ + p*32, DD, 128, s + 30720, tid);
        CP_COMMIT();
    }
    for (int c = 0; c < NC; c++) {
        CP_WAIT1();
        __syncthreads();
        if (c + 2 < NC) {
            uint32_t sn = sb + ((c + 2) % 3) * 40960;
            load32_async(Ah_ + (c+2)*32, DD, 128, sn,         tid);
            load32_async(Al_ + (c+2)*32, DD, 128, sn + 10240, tid);
            load32_async(Bh_ + (c+2)*32, DD, 128, sn + 20480, tid);
            load32_async(Bl_ + (c+2)*32, DD, 128, sn + 30720, tid);
            CP_COMMIT();
        } else {
            CP_COMMIT();
        }
        uint32_t sc = sb + (c % 3) * 40960;
        uint32_t sAh = sc, sAl = sc + 10240, sBh = sc + 20480, sBl = sc + 30720;
        #pragma unroll
        for (int ks = 0; ks < 32; ks += 16) {
            uint32_t ah[4][4], al[4][4], bh[2][4], bl[2][4];
            #pragma unroll
            for (int mf = 0; mf < 4; mf++) {
                lda_frag(ah[mf], sAh, wm + mf*16, ks, lane);
                lda_frag(al[mf], sAl, wm + mf*16, ks, lane);
            }
            ldb_frag(bh[0], sBh, wn,      ks, lane);
            ldb_frag(bh[1], sBh, wn + 16, ks, lane);
            ldb_frag(bl[0], sBl, wn,      ks, lane);
            ldb_frag(bl[1], sBl, wn + 16, ks, lane);
            #pragma unroll
            for (int mf = 0; mf < 4; mf++)
                #pragma unroll
                for (int nf = 0; nf < 4; nf++) {
                    MMA_BF16(acc[mf][nf], ah[mf], bh[nf>>1][(nf&1)*2], bh[nf>>1][(nf&1)*2+1]);
                    MMA_BF16(acc[mf][nf], ah[mf], bl[nf>>1][(nf&1)*2], bl[nf>>1][(nf&1)*2+1]);
                    MMA_BF16(acc[mf][nf], al[mf], bh[nf>>1][(nf&1)*2], bh[nf>>1][(nf&1)*2+1]);
                }
        }
    }
}

// ---------------------------------------------------------------------------
// Fused Q/K/V projection (z = 0/1/2)
// ---------------------------------------------------------------------------
__global__ void __launch_bounds__(256) qkv_proj_kernel(
    const float* __restrict__ bq, const float* __restrict__ bk, const float* __restrict__ bv)
{
    extern __shared__ __align__(16) char smem[];
    const uint32_t sb = smem_u32(smem);
    const int tid = threadIdx.x, wid = tid >> 5, lane = tid & 31;
    const int row0 = blockIdx.y * 128, col0 = blockIdx.x * 128;
    const int wm = (wid >> 2) * 64, wn = (wid & 3) * 32;
    const int z = blockIdx.z;

    const __nv_bfloat16* Ah_ = (z == 0 ? g_xq_h : z == 1 ? g_xk_h : g_xv_h) + (long)row0 * DD;
    const __nv_bfloat16* Al_ = (z == 0 ? g_xq_l : z == 1 ? g_xk_l : g_xv_l) + (long)row0 * DD;
    const __nv_bfloat16* Bh_ = (z == 0 ? g_wq_h : z == 1 ? g_wk_h : g_wv_h) + (long)col0 * DD;
    const __nv_bfloat16* Bl_ = (z == 0 ? g_wq_l : z == 1 ? g_wk_l : g_wv_l) + (long)col0 * DD;
    const float* bias = z == 0 ? bq : z == 1 ? bk : bv;

    float acc[4][4][4];
    #pragma unroll
    for (int i = 0; i < 4; i++)
        #pragma unroll
        for (int j = 0; j < 4; j++)
            #pragma unroll
            for (int q = 0; q < 4; q++) acc[i][j][q] = 0.f;

    proj_mainloop(Ah_, Al_, Bh_, Bl_, sb, tid, lane, wm, wn, acc);

    const int g = lane >> 2, tq = lane & 3;
    __nv_bfloat16* OutHi = z == 0 ? g_Qh : g_Kh;
    __nv_bfloat16* OutLo = z == 0 ? g_Ql : g_Kl;
    #pragma unroll
    for (int mf = 0; mf < 4; mf++) {
        #pragma unroll
        for (int nf = 0; nf < 4; nf++) {
            long r0 = row0 + wm + mf*16 + g, r1 = r0 + 8;
            int  cb = col0 + wn + nf*8 + tq*2;
            float b0 = bias[cb], b1 = bias[cb + 1];
            float v00 = acc[mf][nf][0] + b0, v01 = acc[mf][nf][1] + b1;
            float v10 = acc[mf][nf][2] + b0, v11 = acc[mf][nf][3] + b1;
            if (z < 2) {
                unsigned short h0,h1,l0,l1;
                split2(v00,h0,l0); split2(v01,h1,l1);
                *reinterpret_cast<uint32_t*>(OutHi + r0*DD + cb) = (uint32_t)h0 | ((uint32_t)h1<<16);
                *reinterpret_cast<uint32_t*>(OutLo + r0*DD + cb) = (uint32_t)l0 | ((uint32_t)l1<<16);
                split2(v10,h0,l0); split2(v11,h1,l1);
                *reinterpret_cast<uint32_t*>(OutHi + r1*DD + cb) = (uint32_t)h0 | ((uint32_t)h1<<16);
                *reinterpret_cast<uint32_t*>(OutLo + r1*DD + cb) = (uint32_t)l0 | ((uint32_t)l1<<16);
            } else {
                #pragma unroll
                for (int e = 0; e < 4; e++) {
                    long rr = (e < 2) ? r0 : r1;
                    int  cc = cb + (e & 1);
                    float v = (e==0)?v00:(e==1)?v01:(e==2)?v10:v11;
                    unsigned short h, l; split2(v, h, l);
                    long f = rr * DD + cc;
                    long n = f >> 17, rem = f & 131071;
                    long kpos = rem >> 6, cdim = rem & 63;
                    long addr = n * 131072 + cdim * 2048 + kpos;
                    g_Vth[addr] = __ushort_as_bfloat16(h);
                    g_Vtl[addr] = __ushort_as_bfloat16(l);
                }
            }
        }
    }
}

// ---------------------------------------------------------------------------
// Output projection
// ---------------------------------------------------------------------------
__global__ void __launch_bounds__(256) outproj_kernel(const float* __restrict__ bo)
{
    extern __shared__ __align__(16) char smem[];
    const uint32_t sb = smem_u32(smem);
    const int tid = threadIdx.x, wid = tid >> 5, lane = tid & 31;
    const int row0 = blockIdx.y * 128, col0 = blockIdx.x * 128;
    const int wm = (wid >> 2) * 64, wn = (wid & 3) * 32;

    float acc[4][4][4];
    #pragma unroll
    for (int i = 0; i < 4; i++)
        #pragma unroll
        for (int j = 0; j < 4; j++)
            #pragma unroll
            for (int q = 0; q < 4; q++) acc[i][j][q] = 0.f;

    proj_mainloop(g_ctxh + (long)row0 * DD, g_ctxl + (long)row0 * DD,
                  g_wo_h + (long)col0 * DD, g_wo_l + (long)col0 * DD,
                  sb, tid, lane, wm, wn, acc);

    const int g = lane >> 2, tq = lane & 3;
    #pragma unroll
    for (int mf = 0; mf < 4; mf++)
        #pragma unroll
        for (int nf = 0; nf < 4; nf++) {
            long r0 = row0 + wm + mf*16 + g, r1 = r0 + 8;
            int  cb = col0 + wn + nf*8 + tq*2;
            float b0 = bo[cb], b1 = bo[cb + 1];
            *reinterpret_cast<float2*>(g_proj + r0 * DD + cb) =
                make_float2(acc[mf][nf][0] + b0, acc[mf][nf][1] + b1);
            *reinterpret_cast<float2*>(g_proj + r1 * DD + cb) =
                make_float2(acc[mf][nf][2] + b0, acc[mf][nf][3] + b1);
        }
}

// ---------------------------------------------------------------------------
// Fused flash attention: per CTA (rowblock 128, head z):
//   loop K-tiles: S=QK (3-pass), exp in regs, rowsum +=, ctx += P·V (3-pass)
//   epilogue: rinv out, normalize ctx, split-write ctx
// Warps: 8 x m16 (M-only partition). No attention-matrix traffic.
// smem: Q resident 40960 | 2 stages x (K 40960 + V 40960)
// ---------------------------------------------------------------------------
#define FA_DSMEM (40960 + 2*81920)
__global__ void __launch_bounds__(256, 1) fused_attn_kernel(float* __restrict__ rinv)
{
    extern __shared__ __align__(16) char smem[];
    const uint32_t sb = smem_u32(smem);
    const int tid = threadIdx.x, wid = tid >> 5, lane = tid & 31;
    const int z = blockIdx.y;
    const int row0 = blockIdx.x * 128;
    const int wm = wid * 16;
    const long hoff = (long)z * LL * DHH;      // z*131072

    const __nv_bfloat16* Kh_ = g_Kh + hoff;
    const __nv_bfloat16* Kl_ = g_Kl + hoff;
    const __nv_bfloat16* Vh_ = g_Vth + hoff;
    const __nv_bfloat16* Vl_ = g_Vtl + hoff;

    float pacc[8][4];
    #pragma unroll
    for (int i = 0; i < 8; i++)
        #pragma unroll
        for (int q = 0; q < 4; q++) pacc[i][q] = 0.f;
    float rs0 = 0.f, rs1 = 0.f;

    // prologue: Q resident + stage0, then stage1
    {
        #pragma unroll
        for (int q = 0; q < 2; q++) {
            load32_async(g_Qh + hoff + (long)row0 * 64 + q*32, 64, 128, sb + q*10240,         tid);
            load32_async(g_Ql + hoff + (long)row0 * 64 + q*32, 64, 128, sb + 20480 + q*10240, tid);
        }
        uint32_t st = sb + 40960;
        #pragma unroll
        for (int q = 0; q < 2; q++) {
            load32_async(Kh_ + 0*8192 + q*32, 64, 128, st + q*10240,         tid);
            load32_async(Kl_ + 0*8192 + q*32, 64, 128, st + 20480 + q*10240, tid);
        }
        #pragma unroll
        for (int ch = 0; ch < 4; ch++) {
            load32_async(Vh_ + 0*128 + ch*32, LL, 64, st + 40960 + ch*5120,         tid);
            load32_async(Vl_ + 0*128 + ch*32, LL, 64, st + 40960 + 20480 + ch*5120, tid);
        }
        CP_COMMIT();
        st = sb + 40960 + 81920;
        #pragma unroll
        for (int q = 0; q < 2; q++) {
            load32_async(Kh_ + 1*8192 + q*32, 64, 128, st + q*10240,         tid);
            load32_async(Kl_ + 1*8192 + q*32, 64, 128, st + 20480 + q*10240, tid);
        }
        #pragma unroll
        for (int ch = 0; ch < 4; ch++) {
            load32_async(Vh_ + 1*128 + ch*32, LL, 64, st + 40960 + ch*5120,         tid);
            load32_async(Vl_ + 1*128 + ch*32, LL, 64, st + 40960 + 20480 + ch*5120, tid);
        }
        CP_COMMIT();
    }

    const int NT = LL / 128;   // 16
    for (int jt = 0; jt < NT; jt++) {
        CP_WAIT1();
        __syncthreads();
        uint32_t st = sb + 40960 + (jt & 1) * 81920;
        uint32_t SV = st + 40960;

        // --- QK: S = Q K^T, 3-pass split ---
        float sacc[16][4];
        #pragma unroll
        for (int i = 0; i < 16; i++)
            #pragma unroll
            for (int q = 0; q < 4; q++) sacc[i][q] = 0.f;

        #pragma unroll
        for (int q = 0; q < 2; q++) {
            #pragma unroll
            for (int ks = 0; ks < 32; ks += 16) {
                uint32_t ah[4], al[4];
                lda_frag(ah, sb + q*10240,         wm, ks, lane);
                lda_frag(al, sb + 20480 + q*10240, wm, ks, lane);
                #pragma unroll
                for (int nf = 0; nf < 8; nf++) {
                    uint32_t bh[4], bl[4];
                    ldb_frag(bh, st + q*10240,         nf*16, ks, lane);
                    ldb_frag(bl, st + 20480 + q*10240, nf*16, ks, lane);
                    MMA_BF16(sacc[2*nf],   ah, bh[0], bh[1]);
                    MMA_BF16(sacc[2*nf],   ah, bl[0], bl[1]);
                    MMA_BF16(sacc[2*nf],   al, bh[0], bh[1]);
                    MMA_BF16(sacc[2*nf+1], ah, bh[2], bh[3]);
                    MMA_BF16(sacc[2*nf+1], ah, bl[2], bl[3]);
                    MMA_BF16(sacc[2*nf+1], al, bh[2], bh[3]);
                }
            }
        }

        // --- exp in place + rowsum partials ---
        #pragma unroll
        for (int i = 0; i < 16; i++) {
            sacc[i][0] = __expf(sacc[i][0] * 0.125f);
            sacc[i][1] = __expf(sacc[i][1] * 0.125f);
            sacc[i][2] = __expf(sacc[i][2] * 0.125f);
            sacc[i][3] = __expf(sacc[i][3] * 0.125f);
            rs0 += sacc[i][0] + sacc[i][1];
            rs1 += sacc[i][2] + sacc[i][3];
        }

        // --- PV: ctx += P V, 3-pass; P from registers (acc->A-frag repack) ---
        #pragma unroll
        for (int kt = 0; kt < 8; kt++) {
            uint32_t ah0 = pack_hi(sacc[2*kt][0],   sacc[2*kt][1]);
            uint32_t ah1 = pack_hi(sacc[2*kt][2],   sacc[2*kt][3]);
            uint32_t ah2 = pack_hi(sacc[2*kt+1][0], sacc[2*kt+1][1]);
            uint32_t ah3 = pack_hi(sacc[2*kt+1][2], sacc[2*kt+1][3]);
            uint32_t al0 = pack_lo(sacc[2*kt][0],   sacc[2*kt][1]);
            uint32_t al1 = pack_lo(sacc[2*kt][2],   sacc[2*kt][3]);
            uint32_t al2 = pack_lo(sacc[2*kt+1][0], sacc[2*kt+1][1]);
            uint32_t al3 = pack_lo(sacc[2*kt+1][2], sacc[2*kt+1][3]);
            int ch = kt >> 1, ks = (kt & 1) * 16;
            #pragma unroll
            for (int nf = 0; nf < 4; nf++) {
                uint32_t vh[4], vl[4];
                ldb_frag(vh, SV + ch*5120,         nf*16, ks, lane);
                ldb_frag(vl, SV + 20480 + ch*5120, nf*16, ks, lane);
                MMA_BF16R(pacc[2*nf],   ah0,ah1,ah2,ah3, vh[0], vh[1]);
                MMA_BF16R(pacc[2*nf],   ah0,ah1,ah2,ah3, vl[0], vl[1]);
                MMA_BF16R(pacc[2*nf],   al0,al1,al2,al3, vh[0], vh[1]);
                MMA_BF16R(pacc[2*nf+1], ah0,ah1,ah2,ah3, vh[2], vh[3]);
                MMA_BF16R(pacc[2*nf+1], ah0,ah1,ah2,ah3, vl[2], vl[3]);
                MMA_BF16R(pacc[2*nf+1], al0,al1,al2,al3, vh[2], vh[3]);
            }
        }

        __syncthreads();
        if (jt + 2 < NT) {
            uint32_t sn = sb + 40960 + (jt & 1) * 81920;
            long koff = (long)(jt + 2) * 128;
            #pragma unroll
            for (int q = 0; q < 2; q++) {
                load32_async(Kh_ + koff*64 + q*32, 64, 128, sn + q*10240,         tid);
                load32_async(Kl_ + koff*64 + q*32, 64, 128, sn + 20480 + q*10240, tid);
            }
            #pragma unroll
            for (int ch = 0; ch < 4; ch++) {
                load32_async(Vh_ + koff + ch*32, LL, 64, sn + 40960 + ch*5120,         tid);
                load32_async(Vl_ + koff + ch*32, LL, 64, sn + 40960 + 20480 + ch*5120, tid);
            }
            CP_COMMIT();
        } else {
            CP_COMMIT();
        }
    }

    // --- epilogue: rowsums -> rinv, normalize ctx, write split ctx ---
    const int g = lane >> 2, tq = lane & 3;
    rs0 += __shfl_xor_sync(0xffffffffu, rs0, 1);
    rs0 += __shfl_xor_sync(0xffffffffu, rs0, 2);
    rs1 += __shfl_xor_sync(0xffffffffu, rs1, 1);
    rs1 += __shfl_xor_sync(0xffffffffu, rs1, 2);
    float rv0 = 1.0f / rs0, rv1 = 1.0f / rs1;
    if (tq == 0) {
        rinv[(long)z * LL + row0 + wm + g]     = rv0;
        rinv[(long)z * LL + row0 + wm + g + 8] = rv1;
    }
    long r0 = row0 + wm + g, r1 = r0 + 8;
    #pragma unroll
    for (int nf = 0; nf < 8; nf++) {
        int cb = nf*8 + tq*2;
        long o0 = hoff + r0 * 64 + cb;
        long o1 = hoff + r1 * 64 + cb;
        float v00 = pacc[nf][0] * rv0, v01 = pacc[nf][1] * rv0;
        float v10 = pacc[nf][2] * rv1, v11 = pacc[nf][3] * rv1;
        unsigned short h0,h1,l0,l1;
        split2(v00,h0,l0); split2(v01,h1,l1);
        *reinterpret_cast<uint32_t*>(g_ctxh + o0) = (uint32_t)h0 | ((uint32_t)h1<<16);
        *reinterpret_cast<uint32_t*>(g_ctxl + o0) = (uint32_t)l0 | ((uint32_t)l1<<16);
        split2(v10,h0,l0); split2(v11,h1,l1);
        *reinterpret_cast<uint32_t*>(g_ctxh + o1) = (uint32_t)h0 | ((uint32_t)h1<<16);
        *reinterpret_cast<uint32_t*>(g_ctxl + o1) = (uint32_t)l0 | ((uint32_t)l1<<16);
    }
}

// ---------------------------------------------------------------------------
// Attention write: recompute 128x128 score tile, exp, x rinv, coalesced write
// ---------------------------------------------------------------------------
#define SC_DSMEM (2*40960)
__global__ void __launch_bounds__(256) attn_write_kernel(
    float* __restrict__ attn, const float* __restrict__ rinv)
{
    extern __shared__ __align__(16) char smem[];
    __shared__ float rvs[128];
    const uint32_t sb = smem_u32(smem);
    const int tid = threadIdx.x, wid = tid >> 5, lane = tid & 31;
    const int z = blockIdx.z;
    const int row0 = blockIdx.y * 128, col0 = blockIdx.x * 128;
    const int wm = (wid >> 2) * 64, wn = (wid & 3) * 32;
    const long hoff = (long)z * LL * DHH;

    if (tid < 128) rvs[tid] = rinv[(long)z * LL + row0 + tid];

    float acc[4][4][4];
    #pragma unroll
    for (int i = 0; i < 4; i++)
        #pragma unroll
        for (int j = 0; j < 4; j++)
            #pragma unroll
            for (int q = 0; q < 4; q++) acc[i][j][q] = 0.f;

    #pragma unroll
    for (int c = 0; c < 2; c++) {
        uint32_t s = sb + c * 40960;
        load32_async(g_Qh + hoff + (long)row0 * 64 + c*32, 64, 128, s,         tid);
        load32_async(g_Ql + hoff + (long)row0 * 64 + c*32, 64, 128, s + 10240, tid);
        load32_async(g_Kh + hoff + (long)col0 * 64 + c*32, 64, 128, s + 20480, tid);
        load32_async(g_Kl + hoff + (long)col0 * 64 + c*32, 64, 128, s + 30720, tid);
        CP_COMMIT();
    }

    #pragma unroll
    for (int c = 0; c < 2; c++) {
        if (c == 0) CP_WAIT1(); else CP_WAIT0();
        __syncthreads();
        uint32_t sc = sb + c * 40960;
        uint32_t sAh = sc, sAl = sc + 10240, sBh = sc + 20480, sBl = sc + 30720;
        #pragma unroll
        for (int ks = 0; ks < 32; ks += 16) {
            uint32_t ah[4][4], al[4][4], bh[2][4], bl[2][4];
            #pragma unroll
            for (int mf = 0; mf < 4; mf++) {
                lda_frag(ah[mf], sAh, wm + mf*16, ks, lane);
                lda_frag(al[mf], sAl, wm + mf*16, ks, lane);
            }
            ldb_frag(bh[0], sBh, wn,      ks, lane);
            ldb_frag(bh[1], sBh, wn + 16, ks, lane);
            ldb_frag(bl[0], sBl, wn,      ks, lane);
            ldb_frag(bl[1], sBl, wn + 16, ks, lane);
            #pragma unroll
            for (int mf = 0; mf < 4; mf++)
                #pragma unroll
                for (int nf = 0; nf < 4; nf++) {
                    MMA_BF16(acc[mf][nf], ah[mf], bh[nf>>1][(nf&1)*2], bh[nf>>1][(nf&1)*2+1]);
                    MMA_BF16(acc[mf][nf], ah[mf], bl[nf>>1][(nf&1)*2], bl[nf>>1][(nf&1)*2+1]);
                    MMA_BF16(acc[mf][nf], al[mf], bh[nf>>1][(nf&1)*2], bh[nf>>1][(nf&1)*2+1]);
                }
        }
    }

    __syncthreads();
    float* stg = reinterpret_cast<float*>(smem);
    const int g = lane >> 2, tq = lane & 3;
    #pragma unroll
    for (int mf = 0; mf < 4; mf++) {
        int lr0 = wm + mf*16 + g, lr1 = lr0 + 8;
        float rv0 = rvs[lr0], rv1 = rvs[lr1];
        #pragma unroll
        for (int nf = 0; nf < 4; nf++) {
            int cb = wn + nf*8 + tq*2;
            stg[lr0 * 132 + cb]     = __expf(acc[mf][nf][0] * 0.125f) * rv0;
            stg[lr0 * 132 + cb + 1] = __expf(acc[mf][nf][1] * 0.125f) * rv0;
            stg[lr1 * 132 + cb]     = __expf(acc[mf][nf][2] * 0.125f) * rv1;
            stg[lr1 * 132 + cb + 1] = __expf(acc[mf][nf][3] * 0.125f) * rv1;
        }
    }
    __syncthreads();

    float* ap = attn + (long)z * LL * LL + (long)row0 * LL + col0;
    for (int i = tid; i < 128 * 32; i += 256) {
        int row = i >> 5, q = i & 31;
        float4 v = *reinterpret_cast<const float4*>(stg + row * 132 + q * 4);
        *reinterpret_cast<float4*>(ap + (long)row * LL + q * 4) = v;
    }
}

// ---------------------------------------------------------------------------
// Residual + LayerNorm
// ---------------------------------------------------------------------------
__device__ __forceinline__ float warp_sum(float v) {
    #pragma unroll
    for (int o = 16; o > 0; o >>= 1) v += __shfl_xor_sync(0xffffffffu, v, o);
    return v;
}

__global__ void __launch_bounds__(256) ln_kernel(
    const float* __restrict__ resid,
    const float* __restrict__ gamma, const float* __restrict__ beta,
    float* __restrict__ out)
{
    const long row = blockIdx.x;
    const int tid = threadIdx.x, lane = tid & 31, wid = tid >> 5;
    __shared__ float red[8];

    float4 x = reinterpret_cast<const float4*>(g_proj + row * DD)[tid];
    float4 r = reinterpret_cast<const float4*>(resid + row * DD)[tid];
    x.x += r.x; x.y += r.y; x.z += r.z; x.w += r.w;

    float s = warp_sum(x.x + x.y + x.z + x.w);
    if (lane == 0) red[wid] = s;
    __syncthreads();
    if (wid == 0) {
        float t = (lane < 8) ? red[lane] : 0.f;
        t = warp_sum(t);
        if (lane == 0) red[0] = t;
    }
    __syncthreads();
    const float mu = red[0] * (1.0f / DD);
    __syncthreads();

    float dx = x.x - mu, dy = x.y - mu, dz = x.z - mu, dw = x.w - mu;
    float ss = warp_sum(dx*dx + dy*dy + dz*dz + dw*dw);
    if (lane == 0) red[wid] = ss;
    __syncthreads();
    if (wid == 0) {
        float t = (lane < 8) ? red[lane] : 0.f;
        t = warp_sum(t);
        if (lane == 0) red[0] = t;
    }
    __syncthreads();
    const float rs = rsqrtf(red[0] * (1.0f / DD) + LN_EPS);

    float4 gm = reinterpret_cast<const float4*>(gamma)[tid];
    float4 be = reinterpret_cast<const float4*>(beta)[tid];
    float4 o;
    o.x = dx * rs * gm.x + be.x;
    o.y = dy * rs * gm.y + be.y;
    o.z = dz * rs * gm.z + be.z;
    o.w = dw * rs * gm.w + be.w;
    reinterpret_cast<float4*>(out + row * DD)[tid] = o;
}

// ---------------------------------------------------------------------------
// Launch
// ---------------------------------------------------------------------------
extern "C" void kernel_launch(void* const* d_in, const int* in_sizes, int n_in,
                              void* d_out, int out_size)
{
    const float* query = (const float*)d_in[0];
    const float* key   = (const float*)d_in[1];
    const float* value = (const float*)d_in[2];
    const float* bq = (const float*)d_in[4];
    const float* bk = (const float*)d_in[6];
    const float* bv = (const float*)d_in[8];
    const float* bo = (const float*)d_in[10];
    const float* gamma = (const float*)d_in[11];
    const float* beta  = (const float*)d_in[12];
    const float* Wq = (const float*)d_in[3];
    const float* Wk = (const float*)d_in[5];
    const float* Wv = (const float*)d_in[7];
    const float* Wo = (const float*)d_in[9];

    float* out  = (float*)d_out;
    float* attn = out + OUT_ELEMS;

    float* rinv;
    cudaGetSymbolAddress((void**)&rinv, g_rinv);

    cudaFuncSetAttribute(qkv_proj_kernel,   cudaFuncAttributeMaxDynamicSharedMemorySize, PROJ_DSMEM);
    cudaFuncSetAttribute(outproj_kernel,    cudaFuncAttributeMaxDynamicSharedMemorySize, PROJ_DSMEM);
    cudaFuncSetAttribute(fused_attn_kernel, cudaFuncAttributeMaxDynamicSharedMemorySize, FA_DSMEM);
    cudaFuncSetAttribute(attn_write_kernel, cudaFuncAttributeMaxDynamicSharedMemorySize, SC_DSMEM);

    // 1) fp32 -> split bf16
    dim3 gsi(OUT_ELEMS / 1024, 3);
    split_inputs_kernel<<<gsi, 256>>>(query, key, value);
    dim3 gsw(DD * DD / 1024, 4);
    split_weights_kernel<<<gsw, 256>>>(Wq, Wk, Wv, Wo);

    // 2) Fused Q/K/V projections
    dim3 gp(DD/128, MROWS/128, 3);
    qkv_proj_kernel<<<gp, 256, PROJ_DSMEM>>>(bq, bk, bv);

    // 3) Fused flash attention (ctx + rinv; no attn-matrix traffic)
    dim3 gf(LL/128, BH);
    fused_attn_kernel<<<gf, 256, FA_DSMEM>>>(rinv);

    // 4) Write normalized attention (only attn traffic in the pipeline)
    dim3 gs(LL/128, LL/128, BH);
    attn_write_kernel<<<gs, 256, SC_DSMEM>>>(attn, rinv);

    // 5) Out projection + residual + LN
    dim3 go(DD/128, MROWS/128);
    outproj_kernel<<<go, 256, PROJ_DSMEM>>>(bo);
    ln_kernel<<<MROWS, 256>>>(query, gamma, beta, out);
}

// round 13
// speedup vs baseline: 1.0707x; 1.0707x over previous
#include <cuda_runtime.h>
#include <cuda_bf16.h>
#include <cstdint>

#define BB 2
#define LL 2048
#define DD 1024
#define HH 16
#define DHH 64
#define BH (BB*HH)
#define MROWS (BB*LL)           // 4096
#define OUT_ELEMS (MROWS*DD)
#define LN_EPS 1e-5f

// ---------------------------------------------------------------------------
// Static device scratch
// ---------------------------------------------------------------------------
__device__ __nv_bfloat16 g_xq_h[MROWS*DD], g_xq_l[MROWS*DD];
__device__ __nv_bfloat16 g_xk_h[MROWS*DD], g_xk_l[MROWS*DD];
__device__ __nv_bfloat16 g_xv_h[MROWS*DD], g_xv_l[MROWS*DD];
__device__ __nv_bfloat16 g_wq_h[DD*DD], g_wq_l[DD*DD];
__device__ __nv_bfloat16 g_wk_h[DD*DD], g_wk_l[DD*DD];
__device__ __nv_bfloat16 g_wv_h[DD*DD], g_wv_l[DD*DD];
__device__ __nv_bfloat16 g_wo_h[DD*DD], g_wo_l[DD*DD];
__device__ __nv_bfloat16 g_Qh[MROWS*DD], g_Ql[MROWS*DD];
__device__ __nv_bfloat16 g_Kh[MROWS*DD], g_Kl[MROWS*DD];
__device__ __nv_bfloat16 g_Vth[MROWS*DD], g_Vtl[MROWS*DD];  // [n][c][k]
__device__ __nv_bfloat16 g_ctxh[MROWS*DD], g_ctxl[MROWS*DD];
__device__ float g_part[(long)BH*LL*16];
__device__ float g_rinv[(long)BH*LL];
__device__ float g_proj[MROWS*DD];

// ---------------------------------------------------------------------------
// PTX helpers
// ---------------------------------------------------------------------------
__device__ __forceinline__ uint32_t smem_u32(const void* p) {
    uint32_t a;
    asm("{ .reg .u64 t; cvta.to.shared.u64 t, %1; cvt.u32.u64 %0, t; }" : "=r"(a) : "l"(p));
    return a;
}

#define LDMX4(r0,r1,r2,r3,addr) \
    asm volatile("ldmatrix.sync.aligned.m8n8.x4.shared.b16 {%0,%1,%2,%3}, [%4];" \
        : "=r"(r0), "=r"(r1), "=r"(r2), "=r"(r3) : "r"(addr))

#define MMA_BF16(d, a, b0v, b1v) \
    asm volatile("mma.sync.aligned.m16n8k16.row.col.f32.bf16.bf16.f32 " \
        "{%0,%1,%2,%3},{%4,%5,%6,%7},{%8,%9},{%0,%1,%2,%3};" \
        : "+f"((d)[0]), "+f"((d)[1]), "+f"((d)[2]), "+f"((d)[3]) \
        : "r"((a)[0]), "r"((a)[1]), "r"((a)[2]), "r"((a)[3]), "r"(b0v), "r"(b1v))

__device__ __forceinline__ void cp16(uint32_t dst, const void* src) {
    asm volatile("cp.async.cg.shared.global [%0], [%1], 16;" :: "r"(dst), "l"(src));
}
#define CP_COMMIT() asm volatile("cp.async.commit_group;" ::: "memory")
#define CP_WAIT0()  asm volatile("cp.async.wait_group 0;" ::: "memory")
#define CP_WAIT1()  asm volatile("cp.async.wait_group 1;" ::: "memory")

__device__ __forceinline__ void lda_frag(uint32_t a[4], uint32_t base, int mbase, int ks, int lane) {
    int row = mbase + (lane & 7) + ((lane >> 3) & 1) * 8;
    int col = ks + (lane >> 4) * 8;
    LDMX4(a[0], a[1], a[2], a[3], base + row * 80 + col * 2);
}
__device__ __forceinline__ void ldb_frag(uint32_t b[4], uint32_t base, int nbase, int ks, int lane) {
    int r = lane & 7, gp = lane >> 3;
    int n = nbase + (gp >> 1) * 8 + r;
    int col = ks + (gp & 1) * 8;
    LDMX4(b[0], b[1], b[2], b[3], base + n * 80 + col * 2);
}

__device__ __forceinline__ void load32_async(const __nv_bfloat16* __restrict__ src, long ld,
                                             int R, uint32_t base, int tid) {
    for (int i = tid; i < R * 4; i += 256) {
        int row = i >> 2, q = i & 3;
        cp16(base + row * 80 + q * 16, src + (long)row * ld + q * 8);
    }
}

__device__ __forceinline__ void split2(float v, unsigned short& h, unsigned short& l) {
    __nv_bfloat16 bh = __float2bfloat16(v);
    __nv_bfloat16 bl = __float2bfloat16(v - __bfloat162float(bh));
    h = __bfloat16_as_ushort(bh); l = __bfloat16_as_ushort(bl);
}

// ---------------------------------------------------------------------------
// fp32 -> (hi,lo) split (merged launches)
// ---------------------------------------------------------------------------
__global__ void __launch_bounds__(256) split_inputs_kernel(
    const float* __restrict__ s0, const float* __restrict__ s1, const float* __restrict__ s2)
{
    const int which = blockIdx.y;
    const float* src = which == 0 ? s0 : which == 1 ? s1 : s2;
    __nv_bfloat16* hi = which == 0 ? g_xq_h : which == 1 ? g_xk_h : g_xv_h;
    __nv_bfloat16* lo = which == 0 ? g_xq_l : which == 1 ? g_xk_l : g_xv_l;
    long i = (long)blockIdx.x * 256 + threadIdx.x;
    float4 v = reinterpret_cast<const float4*>(src)[i];
    unsigned short h0,h1,h2,h3,l0,l1,l2,l3;
    split2(v.x,h0,l0); split2(v.y,h1,l1); split2(v.z,h2,l2); split2(v.w,h3,l3);
    uint2 uh, ul;
    uh.x = (uint32_t)h0 | ((uint32_t)h1 << 16); uh.y = (uint32_t)h2 | ((uint32_t)h3 << 16);
    ul.x = (uint32_t)l0 | ((uint32_t)l1 << 16); ul.y = (uint32_t)l2 | ((uint32_t)l3 << 16);
    reinterpret_cast<uint2*>(hi)[i] = uh;
    reinterpret_cast<uint2*>(lo)[i] = ul;
}

__global__ void __launch_bounds__(256) split_weights_kernel(
    const float* __restrict__ s0, const float* __restrict__ s1,
    const float* __restrict__ s2, const float* __restrict__ s3)
{
    const int which = blockIdx.y;
    const float* src = which == 0 ? s0 : which == 1 ? s1 : which == 2 ? s2 : s3;
    __nv_bfloat16* hi = which == 0 ? g_wq_h : which == 1 ? g_wk_h : which == 2 ? g_wv_h : g_wo_h;
    __nv_bfloat16* lo = which == 0 ? g_wq_l : which == 1 ? g_wk_l : which == 2 ? g_wv_l : g_wo_l;
    long i = (long)blockIdx.x * 256 + threadIdx.x;
    float4 v = reinterpret_cast<const float4*>(src)[i];
    unsigned short h0,h1,h2,h3,l0,l1,l2,l3;
    split2(v.x,h0,l0); split2(v.y,h1,l1); split2(v.z,h2,l2); split2(v.w,h3,l3);
    uint2 uh, ul;
    uh.x = (uint32_t)h0 | ((uint32_t)h1 << 16); uh.y = (uint32_t)h2 | ((uint32_t)h3 << 16);
    ul.x = (uint32_t)l0 | ((uint32_t)l1 << 16); ul.y = (uint32_t)l2 | ((uint32_t)l3 << 16);
    reinterpret_cast<uint2*>(hi)[i] = uh;
    reinterpret_cast<uint2*>(lo)[i] = ul;
}

// ---------------------------------------------------------------------------
// Shared 2-stage GEMM mainloop (block 128x128, BK=32, K=1024), 80KB smem
// -> 2 CTAs/SM with reg cap 128
// ---------------------------------------------------------------------------
#define PROJ_DSMEM (2*40960)
__device__ __forceinline__ void proj_mainloop(
    const __nv_bfloat16* __restrict__ Ah_, const __nv_bfloat16* __restrict__ Al_,
    const __nv_bfloat16* __restrict__ Bh_, const __nv_bfloat16* __restrict__ Bl_,
    uint32_t sb, int tid, int lane, int wm, int wn, float acc[4][4][4])
{
    const int NC = DD / 32;   // 32
    #pragma unroll
    for (int p = 0; p < 2; p++) {
        uint32_t s = sb + p * 40960;
        load32_async(Ah_ + p*32, DD, 128, s,         tid);
        load32_async(Al_ + p*32, DD, 128, s + 10240, tid);
        load32_async(Bh_ + p*32, DD, 128, s + 20480, tid);
        load32_async(Bl_ + p*32, DD, 128, s + 30720, tid);
        CP_COMMIT();
    }
    for (int c = 0; c < NC; c++) {
        CP_WAIT1();
        __syncthreads();
        uint32_t sc = sb + (c & 1) * 40960;
        uint32_t sAh = sc, sAl = sc + 10240, sBh = sc + 20480, sBl = sc + 30720;
        #pragma unroll
        for (int ks = 0; ks < 32; ks += 16) {
            uint32_t ah[4][4], al[4][4], bh[2][4], bl[2][4];
            #pragma unroll
            for (int mf = 0; mf < 4; mf++) {
                lda_frag(ah[mf], sAh, wm + mf*16, ks, lane);
                lda_frag(al[mf], sAl, wm + mf*16, ks, lane);
            }
            ldb_frag(bh[0], sBh, wn,      ks, lane);
            ldb_frag(bh[1], sBh, wn + 16, ks, lane);
            ldb_frag(bl[0], sBl, wn,      ks, lane);
            ldb_frag(bl[1], sBl, wn + 16, ks, lane);
            #pragma unroll
            for (int mf = 0; mf < 4; mf++)
                #pragma unroll
                for (int nf = 0; nf < 4; nf++) {
                    MMA_BF16(acc[mf][nf], ah[mf], bh[nf>>1][(nf&1)*2], bh[nf>>1][(nf&1)*2+1]);
                    MMA_BF16(acc[mf][nf], ah[mf], bl[nf>>1][(nf&1)*2], bl[nf>>1][(nf&1)*2+1]);
                    MMA_BF16(acc[mf][nf], al[mf], bh[nf>>1][(nf&1)*2], bh[nf>>1][(nf&1)*2+1]);
                }
        }
        __syncthreads();
        if (c + 2 < NC) {
            uint32_t sn = sb + (c & 1) * 40960;   // buffer just freed
            load32_async(Ah_ + (c+2)*32, DD, 128, sn,         tid);
            load32_async(Al_ + (c+2)*32, DD, 128, sn + 10240, tid);
            load32_async(Bh_ + (c+2)*32, DD, 128, sn + 20480, tid);
            load32_async(Bl_ + (c+2)*32, DD, 128, sn + 30720, tid);
            CP_COMMIT();
        } else {
            CP_COMMIT();
        }
    }
}

// ---------------------------------------------------------------------------
// Fused Q/K/V projection (z = 0/1/2)
// ---------------------------------------------------------------------------
__global__ void __launch_bounds__(256, 2) qkv_proj_kernel(
    const float* __restrict__ bq, const float* __restrict__ bk, const float* __restrict__ bv)
{
    extern __shared__ __align__(16) char smem[];
    const uint32_t sb = smem_u32(smem);
    const int tid = threadIdx.x, wid = tid >> 5, lane = tid & 31;
    const int row0 = blockIdx.y * 128, col0 = blockIdx.x * 128;
    const int wm = (wid >> 2) * 64, wn = (wid & 3) * 32;
    const int z = blockIdx.z;

    const __nv_bfloat16* Ah_ = (z == 0 ? g_xq_h : z == 1 ? g_xk_h : g_xv_h) + (long)row0 * DD;
    const __nv_bfloat16* Al_ = (z == 0 ? g_xq_l : z == 1 ? g_xk_l : g_xv_l) + (long)row0 * DD;
    const __nv_bfloat16* Bh_ = (z == 0 ? g_wq_h : z == 1 ? g_wk_h : g_wv_h) + (long)col0 * DD;
    const __nv_bfloat16* Bl_ = (z == 0 ? g_wq_l : z == 1 ? g_wk_l : g_wv_l) + (long)col0 * DD;
    const float* bias = z == 0 ? bq : z == 1 ? bk : bv;

    float acc[4][4][4];
    #pragma unroll
    for (int i = 0; i < 4; i++)
        #pragma unroll
        for (int j = 0; j < 4; j++)
            #pragma unroll
            for (int q = 0; q < 4; q++) acc[i][j][q] = 0.f;

    proj_mainloop(Ah_, Al_, Bh_, Bl_, sb, tid, lane, wm, wn, acc);

    const int g = lane >> 2, tq = lane & 3;
    __nv_bfloat16* OutHi = z == 0 ? g_Qh : g_Kh;
    __nv_bfloat16* OutLo = z == 0 ? g_Ql : g_Kl;
    #pragma unroll
    for (int mf = 0; mf < 4; mf++) {
        #pragma unroll
        for (int nf = 0; nf < 4; nf++) {
            long r0 = row0 + wm + mf*16 + g, r1 = r0 + 8;
            int  cb = col0 + wn + nf*8 + tq*2;
            float b0 = bias[cb], b1 = bias[cb + 1];
            float v00 = acc[mf][nf][0] + b0, v01 = acc[mf][nf][1] + b1;
            float v10 = acc[mf][nf][2] + b0, v11 = acc[mf][nf][3] + b1;
            if (z < 2) {
                unsigned short h0,h1,l0,l1;
                split2(v00,h0,l0); split2(v01,h1,l1);
                *reinterpret_cast<uint32_t*>(OutHi + r0*DD + cb) = (uint32_t)h0 | ((uint32_t)h1<<16);
                *reinterpret_cast<uint32_t*>(OutLo + r0*DD + cb) = (uint32_t)l0 | ((uint32_t)l1<<16);
                split2(v10,h0,l0); split2(v11,h1,l1);
                *reinterpret_cast<uint32_t*>(OutHi + r1*DD + cb) = (uint32_t)h0 | ((uint32_t)h1<<16);
                *reinterpret_cast<uint32_t*>(OutLo + r1*DD + cb) = (uint32_t)l0 | ((uint32_t)l1<<16);
            } else {
                #pragma unroll
                for (int e = 0; e < 4; e++) {
                    long rr = (e < 2) ? r0 : r1;
                    int  cc = cb + (e & 1);
                    float v = (e==0)?v00:(e==1)?v01:(e==2)?v10:v11;
                    unsigned short h, l; split2(v, h, l);
                    long f = rr * DD + cc;
                    long n = f >> 17, rem = f & 131071;
                    long kpos = rem >> 6, cdim = rem & 63;
                    long addr = n * 131072 + cdim * 2048 + kpos;
                    g_Vth[addr] = __ushort_as_bfloat16(h);
                    g_Vtl[addr] = __ushort_as_bfloat16(l);
                }
            }
        }
    }
}

// ---------------------------------------------------------------------------
// Output projection
// ---------------------------------------------------------------------------
__global__ void __launch_bounds__(256, 2) outproj_kernel(const float* __restrict__ bo)
{
    extern __shared__ __align__(16) char smem[];
    const uint32_t sb = smem_u32(smem);
    const int tid = threadIdx.x, wid = tid >> 5, lane = tid & 31;
    const int row0 = blockIdx.y * 128, col0 = blockIdx.x * 128;
    const int wm = (wid >> 2) * 64, wn = (wid & 3) * 32;

    float acc[4][4][4];
    #pragma unroll
    for (int i = 0; i < 4; i++)
        #pragma unroll
        for (int j = 0; j < 4; j++)
            #pragma unroll
            for (int q = 0; q < 4; q++) acc[i][j][q] = 0.f;

    proj_mainloop(g_ctxh + (long)row0 * DD, g_ctxl + (long)row0 * DD,
                  g_wo_h + (long)col0 * DD, g_wo_l + (long)col0 * DD,
                  sb, tid, lane, wm, wn, acc);

    const int g = lane >> 2, tq = lane & 3;
    #pragma unroll
    for (int mf = 0; mf < 4; mf++)
        #pragma unroll
        for (int nf = 0; nf < 4; nf++) {
            long r0 = row0 + wm + mf*16 + g, r1 = r0 + 8;
            int  cb = col0 + wn + nf*8 + tq*2;
            float b0 = bo[cb], b1 = bo[cb + 1];
            *reinterpret_cast<float2*>(g_proj + r0 * DD + cb) =
                make_float2(acc[mf][nf][0] + b0, acc[mf][nf][1] + b1);
            *reinterpret_cast<float2*>(g_proj + r1 * DD + cb) =
                make_float2(acc[mf][nf][2] + b0, acc[mf][nf][3] + b1);
        }
}

// ---------------------------------------------------------------------------
// Scores: 128x128 tile per head, K=64 (both chunks prefetched).
// Epilogue: exp(s/8) staged in smem, coalesced writes + row partial sums.
// 80KB smem + (256,2) -> 2 CTAs/SM
// ---------------------------------------------------------------------------
#define SC_DSMEM (2*40960)
__global__ void __launch_bounds__(256, 2) scores_mma_kernel(
    float* __restrict__ attn, float* __restrict__ part)
{
    extern __shared__ __align__(16) char smem[];
    __shared__ float srow[128][4];
    const uint32_t sb = smem_u32(smem);
    const int tid = threadIdx.x, wid = tid >> 5, lane = tid & 31;
    const int z = blockIdx.z;
    const int row0 = blockIdx.y * 128, col0 = blockIdx.x * 128;
    const int wm = (wid >> 2) * 64, wn = (wid & 3) * 32;
    const long hoff = (long)z * LL * DHH;

    float acc[4][4][4];
    #pragma unroll
    for (int i = 0; i < 4; i++)
        #pragma unroll
        for (int j = 0; j < 4; j++)
            #pragma unroll
            for (int q = 0; q < 4; q++) acc[i][j][q] = 0.f;

    #pragma unroll
    for (int c = 0; c < 2; c++) {
        uint32_t s = sb + c * 40960;
        load32_async(g_Qh + hoff + (long)row0 * 64 + c*32, 64, 128, s,         tid);
        load32_async(g_Ql + hoff + (long)row0 * 64 + c*32, 64, 128, s + 10240, tid);
        load32_async(g_Kh + hoff + (long)col0 * 64 + c*32, 64, 128, s + 20480, tid);
        load32_async(g_Kl + hoff + (long)col0 * 64 + c*32, 64, 128, s + 30720, tid);
        CP_COMMIT();
    }

    #pragma unroll
    for (int c = 0; c < 2; c++) {
        if (c == 0) CP_WAIT1(); else CP_WAIT0();
        __syncthreads();
        uint32_t sc = sb + c * 40960;
        uint32_t sAh = sc, sAl = sc + 10240, sBh = sc + 20480, sBl = sc + 30720;
        #pragma unroll
        for (int ks = 0; ks < 32; ks += 16) {
            uint32_t ah[4][4], al[4][4], bh[2][4], bl[2][4];
            #pragma unroll
            for (int mf = 0; mf < 4; mf++) {
                lda_frag(ah[mf], sAh, wm + mf*16, ks, lane);
                lda_frag(al[mf], sAl, wm + mf*16, ks, lane);
            }
            ldb_frag(bh[0], sBh, wn,      ks, lane);
            ldb_frag(bh[1], sBh, wn + 16, ks, lane);
            ldb_frag(bl[0], sBl, wn,      ks, lane);
            ldb_frag(bl[1], sBl, wn + 16, ks, lane);
            #pragma unroll
            for (int mf = 0; mf < 4; mf++)
                #pragma unroll
                for (int nf = 0; nf < 4; nf++) {
                    MMA_BF16(acc[mf][nf], ah[mf], bh[nf>>1][(nf&1)*2], bh[nf>>1][(nf&1)*2+1]);
                    MMA_BF16(acc[mf][nf], ah[mf], bl[nf>>1][(nf&1)*2], bl[nf>>1][(nf&1)*2+1]);
                    MMA_BF16(acc[mf][nf], al[mf], bh[nf>>1][(nf&1)*2], bh[nf>>1][(nf&1)*2+1]);
                }
        }
    }

    // epilogue: exp -> smem staging (row stride 132 f32), row partials
    __syncthreads();
    float* stg = reinterpret_cast<float*>(smem);
    const int g = lane >> 2, tq = lane & 3;
    #pragma unroll
    for (int mf = 0; mf < 4; mf++) {
        float s0 = 0.f, s1 = 0.f;
        int lr0 = wm + mf*16 + g, lr1 = lr0 + 8;
        #pragma unroll
        for (int nf = 0; nf < 4; nf++) {
            int cb = wn + nf*8 + tq*2;
            float e00 = __expf(acc[mf][nf][0] * 0.125f);
            float e01 = __expf(acc[mf][nf][1] * 0.125f);
            float e10 = __expf(acc[mf][nf][2] * 0.125f);
            float e11 = __expf(acc[mf][nf][3] * 0.125f);
            s0 += e00 + e01; s1 += e10 + e11;
            stg[lr0 * 132 + cb] = e00; stg[lr0 * 132 + cb + 1] = e01;
            stg[lr1 * 132 + cb] = e10; stg[lr1 * 132 + cb + 1] = e11;
        }
        s0 += __shfl_xor_sync(0xffffffffu, s0, 1);
        s0 += __shfl_xor_sync(0xffffffffu, s0, 2);
        s1 += __shfl_xor_sync(0xffffffffu, s1, 1);
        s1 += __shfl_xor_sync(0xffffffffu, s1, 2);
        if (tq == 0) {
            srow[lr0][wid & 3] = s0;
            srow[lr1][wid & 3] = s1;
        }
    }
    __syncthreads();

    float* ap = attn + (long)z * LL * LL + (long)row0 * LL + col0;
    for (int i = tid; i < 128 * 32; i += 256) {
        int row = i >> 5, q = i & 31;
        float4 v = *reinterpret_cast<const float4*>(stg + row * 132 + q * 4);
        *reinterpret_cast<float4*>(ap + (long)row * LL + q * 4) = v;
    }
    if (tid < 128) {
        float t = srow[tid][0] + srow[tid][1] + srow[tid][2] + srow[tid][3];
        part[((long)z * LL + row0 + tid) * 16 + blockIdx.x] = t;
    }
}

// ---------------------------------------------------------------------------
// Row reciprocal
// ---------------------------------------------------------------------------
__global__ void __launch_bounds__(256) rowinv_kernel(const float* __restrict__ part,
                                                     float* __restrict__ rinv) {
    long i = (long)blockIdx.x * 256 + threadIdx.x;
    float s = 0.f;
    #pragma unroll
    for (int t = 0; t < 16; t++) s += part[i * 16 + t];
    rinv[i] = 1.0f / s;
}

// ---------------------------------------------------------------------------
// AV, 3-stage cp.async (100KB), (256,2) -> 2 CTAs/SM:
// normalize attn chunk (smem-staged), write back, split, MMA vs Vt.
// Dyn smem: Ah(10240) Al(10240), stages at 20480 + s*26624:
//   ATTN f32(16384) Vh(5120) Vl(5120)
// ---------------------------------------------------------------------------
#define AV_DSMEM (20480 + 3*26624)
__global__ void __launch_bounds__(256, 2) av_mma_kernel(
    float* __restrict__ attn, const float* __restrict__ rinv)
{
    extern __shared__ __align__(16) char smem[];
    __shared__ float rvs[128];
    const uint32_t sb = smem_u32(smem);
    const int tid = threadIdx.x, wid = tid >> 5, lane = tid & 31;
    const int z = blockIdx.y;
    const int row0 = blockIdx.x * 128;
    const int wm = (wid >> 2) * 64, wn = (wid & 3) * 16;

    float* ab = attn + (long)z * LL * LL + (long)row0 * LL;
    const __nv_bfloat16* vh = g_Vth + (long)z * LL * DHH;
    const __nv_bfloat16* vl = g_Vtl + (long)z * LL * DHH;

    if (tid < 128) rvs[tid] = rinv[(long)z * LL + row0 + tid];

    float acc[4][2][4];
    #pragma unroll
    for (int i = 0; i < 4; i++)
        #pragma unroll
        for (int j = 0; j < 2; j++)
            #pragma unroll
            for (int q = 0; q < 4; q++) acc[i][j][q] = 0.f;

    const uint32_t AH = sb, AL = sb + 10240;
    const int NC = LL / 32;   // 64

    #pragma unroll
    for (int p = 0; p < 2; p++) {
        uint32_t s = sb + 20480 + p * 26624;
        long goff = (long)p * 32;
        for (int i = tid; i < 1024; i += 256) {
            int row = i >> 3, q = i & 7;
            cp16(s + row * 128 + q * 16, ab + (long)row * LL + goff + q * 4);
        }
        load32_async(vh + goff, LL, 64, s + 16384, tid);
        load32_async(vl + goff, LL, 64, s + 21504, tid);
        CP_COMMIT();
    }

    for (int c = 0; c < NC; c++) {
        CP_WAIT1();
        __syncthreads();
        if (c + 2 < NC) {
            uint32_t sn = sb + 20480 + ((c + 2) % 3) * 26624;
            long goff = (long)(c + 2) * 32;
            for (int i = tid; i < 1024; i += 256) {
                int row = i >> 3, q = i & 7;
                cp16(sn + row * 128 + q * 16, ab + (long)row * LL + goff + q * 4);
            }
            load32_async(vh + goff, LL, 64, sn + 16384, tid);
            load32_async(vl + goff, LL, 64, sn + 21504, tid);
            CP_COMMIT();
        } else {
            CP_COMMIT();
        }
        uint32_t sc = sb + 20480 + (c % 3) * 26624;
        char* stg = smem + (sc - sb);

        for (int i = tid; i < 1024; i += 256) {
            int row = i >> 3, q = i & 7;
            float4 v = *reinterpret_cast<const float4*>(stg + row * 128 + q * 16);
            float r = rvs[row];
            v.x *= r; v.y *= r; v.z *= r; v.w *= r;
            *reinterpret_cast<float4*>(ab + (long)row * LL + (long)c * 32 + q * 4) = v;
            unsigned short h0,h1,h2,h3,l0,l1,l2,l3;
            split2(v.x,h0,l0); split2(v.y,h1,l1); split2(v.z,h2,l2); split2(v.w,h3,l3);
            uint2 uh, ul;
            uh.x = (uint32_t)h0 | ((uint32_t)h1 << 16);
            uh.y = (uint32_t)h2 | ((uint32_t)h3 << 16);
            ul.x = (uint32_t)l0 | ((uint32_t)l1 << 16);
            ul.y = (uint32_t)l2 | ((uint32_t)l3 << 16);
            *reinterpret_cast<uint2*>(smem + row * 80 + q * 8)         = uh;
            *reinterpret_cast<uint2*>(smem + 10240 + row * 80 + q * 8) = ul;
        }
        __syncthreads();

        uint32_t sBh = sc + 16384, sBl = sc + 21504;
        #pragma unroll
        for (int ks = 0; ks < 32; ks += 16) {
            uint32_t ah[4][4], al[4][4], bh[4], bl[4];
            #pragma unroll
            for (int mf = 0; mf < 4; mf++) {
                lda_frag(ah[mf], AH, wm + mf*16, ks, lane);
                lda_frag(al[mf], AL, wm + mf*16, ks, lane);
            }
            ldb_frag(bh, sBh, wn, ks, lane);
            ldb_frag(bl, sBl, wn, ks, lane);
            #pragma unroll
            for (int mf = 0; mf < 4; mf++)
                #pragma unroll
                for (int nf = 0; nf < 2; nf++) {
                    MMA_BF16(acc[mf][nf], ah[mf], bh[nf*2], bh[nf*2+1]);
                    MMA_BF16(acc[mf][nf], ah[mf], bl[nf*2], bl[nf*2+1]);
                    MMA_BF16(acc[mf][nf], al[mf], bh[nf*2], bh[nf*2+1]);
                }
        }
    }

    const int g = lane >> 2, tq = lane & 3;
    #pragma unroll
    for (int mf = 0; mf < 4; mf++)
        #pragma unroll
        for (int nf = 0; nf < 2; nf++) {
            long r0 = row0 + wm + mf*16 + g, r1 = r0 + 8;
            int cb = wn + nf*8 + tq*2;
            unsigned short h0,h1,l0,l1;
            long o0 = (long)z * LL * DHH + r0 * 64 + cb;
            long o1 = (long)z * LL * DHH + r1 * 64 + cb;
            split2(acc[mf][nf][0], h0, l0); split2(acc[mf][nf][1], h1, l1);
            *reinterpret_cast<uint32_t*>(g_ctxh + o0) = (uint32_t)h0 | ((uint32_t)h1<<16);
            *reinterpret_cast<uint32_t*>(g_ctxl + o0) = (uint32_t)l0 | ((uint32_t)l1<<16);
            split2(acc[mf][nf][2], h0, l0); split2(acc[mf][nf][3], h1, l1);
            *reinterpret_cast<uint32_t*>(g_ctxh + o1) = (uint32_t)h0 | ((uint32_t)h1<<16);
            *reinterpret_cast<uint32_t*>(g_ctxl + o1) = (uint32_t)l0 | ((uint32_t)l1<<16);
        }
}

// ---------------------------------------------------------------------------
// Residual + LayerNorm
// ---------------------------------------------------------------------------
__device__ __forceinline__ float warp_sum(float v) {
    #pragma unroll
    for (int o = 16; o > 0; o >>= 1) v += __shfl_xor_sync(0xffffffffu, v, o);
    return v;
}

__global__ void __launch_bounds__(256) ln_kernel(
    const float* __restrict__ resid,
    const float* __restrict__ gamma, const float* __restrict__ beta,
    float* __restrict__ out)
{
    const long row = blockIdx.x;
    const int tid = threadIdx.x, lane = tid & 31, wid = tid >> 5;
    __shared__ float red[8];

    float4 x = reinterpret_cast<const float4*>(g_proj + row * DD)[tid];
    float4 r = reinterpret_cast<const float4*>(resid + row * DD)[tid];
    x.x += r.x; x.y += r.y; x.z += r.z; x.w += r.w;

    float s = warp_sum(x.x + x.y + x.z + x.w);
    if (lane == 0) red[wid] = s;
    __syncthreads();
    if (wid == 0) {
        float t = (lane < 8) ? red[lane] : 0.f;
        t = warp_sum(t);
        if (lane == 0) red[0] = t;
    }
    __syncthreads();
    const float mu = red[0] * (1.0f / DD);
    __syncthreads();

    float dx = x.x - mu, dy = x.y - mu, dz = x.z - mu, dw = x.w - mu;
    float ss = warp_sum(dx*dx + dy*dy + dz*dz + dw*dw);
    if (lane == 0) red[wid] = ss;
    __syncthreads();
    if (wid == 0) {
        float t = (lane < 8) ? red[lane] : 0.f;
        t = warp_sum(t);
        if (lane == 0) red[0] = t;
    }
    __syncthreads();
    const float rs = rsqrtf(red[0] * (1.0f / DD) + LN_EPS);

    float4 gm = reinterpret_cast<const float4*>(gamma)[tid];
    float4 be = reinterpret_cast<const float4*>(beta)[tid];
    float4 o;
    o.x = dx * rs * gm.x + be.x;
    o.y = dy * rs * gm.y + be.y;
    o.z = dz * rs * gm.z + be.z;
    o.w = dw * rs * gm.w + be.w;
    reinterpret_cast<float4*>(out + row * DD)[tid] = o;
}

// ---------------------------------------------------------------------------
// Launch
// ---------------------------------------------------------------------------
extern "C" void kernel_launch(void* const* d_in, const int* in_sizes, int n_in,
                              void* d_out, int out_size)
{
    const float* query = (const float*)d_in[0];
    const float* key   = (const float*)d_in[1];
    const float* value = (const float*)d_in[2];
    const float* Wq = (const float*)d_in[3];
    const float* bq = (const float*)d_in[4];
    const float* Wk = (const float*)d_in[5];
    const float* bk = (const float*)d_in[6];
    const float* Wv = (const float*)d_in[7];
    const float* bv = (const float*)d_in[8];
    const float* Wo = (const float*)d_in[9];
    const float* bo = (const float*)d_in[10];
    const float* gamma = (const float*)d_in[11];
    const float* beta  = (const float*)d_in[12];

    float* out  = (float*)d_out;
    float* attn = out + OUT_ELEMS;

    float *part, *rinv;
    cudaGetSymbolAddress((void**)&part, g_part);
    cudaGetSymbolAddress((void**)&rinv, g_rinv);

    cudaFuncSetAttribute(qkv_proj_kernel,   cudaFuncAttributeMaxDynamicSharedMemorySize, PROJ_DSMEM);
    cudaFuncSetAttribute(outproj_kernel,    cudaFuncAttributeMaxDynamicSharedMemorySize, PROJ_DSMEM);
    cudaFuncSetAttribute(scores_mma_kernel, cudaFuncAttributeMaxDynamicSharedMemorySize, SC_DSMEM);
    cudaFuncSetAttribute(av_mma_kernel,     cudaFuncAttributeMaxDynamicSharedMemorySize, AV_DSMEM);

    // 1) fp32 -> split bf16
    dim3 gsi(OUT_ELEMS / 1024, 3);
    split_inputs_kernel<<<gsi, 256>>>(query, key, value);
    dim3 gsw(DD * DD / 1024, 4);
    split_weights_kernel<<<gsw, 256>>>(Wq, Wk, Wv, Wo);

    // 2) Fused Q/K/V projections
    dim3 gp(DD/128, MROWS/128, 3);
    qkv_proj_kernel<<<gp, 256, PROJ_DSMEM>>>(bq, bk, bv);

    // 3) Scores + exp + partial sums
    dim3 gs(LL/128, LL/128, BH);
    scores_mma_kernel<<<gs, 256, SC_DSMEM>>>(attn, part);

    // 4) Row reciprocals
    rowinv_kernel<<<(BH*LL)/256, 256>>>(part, rinv);

    // 5) AV (normalizes attention in place, writes ctx hi/lo)
    dim3 ga(LL/128, BH);
    av_mma_kernel<<<ga, 256, AV_DSMEM>>>(attn, rinv);

    // 6) Out projection + residual + LN
    dim3 go(DD/128, MROWS/128);
    outproj_kernel<<<go, 256, PROJ_DSMEM>>>(bo);
    ln_kernel<<<MROWS, 256>>>(query, gamma, beta, out);
}